// round 4
// baseline (speedup 1.0000x reference)
#include <cuda_runtime.h>

// TemporalAttention_43722767073503
//
// Reference output = log_softmax over a size-1 axis of the (B,T,1) score
// tensor -> identically 0 for all finite inputs. All upstream GEMM/tanh work
// is dead code; exact answer is 524288 zeros.
//
// We are at the kernel-launch overhead floor (~5000 cyc ≈ 4.5us chip model;
// measured 3.9us kernel, DRAM 0%, L2 5%). This round: minimal branch-free
// exact-cover kernel — 128 CTAs x 1024 threads, one unconditional STG.128
// each (524288 floats = 131072 float4 = 128*1024 exactly). Shortest possible
// SASS body and launch ramp.

__global__ void zero_exact_f4(float4* __restrict__ out) {
    out[blockIdx.x * blockDim.x + threadIdx.x] =
        make_float4(0.f, 0.f, 0.f, 0.f);
}

// General fallback (never taken for this problem's out_size, kept for safety).
__global__ void zero_general(float* __restrict__ out, int n) {
    for (int i = blockIdx.x * blockDim.x + threadIdx.x; i < n;
         i += gridDim.x * blockDim.x) {
        out[i] = 0.f;
    }
}

extern "C" void kernel_launch(void* const* d_in, const int* in_sizes, int n_in,
                              void* d_out, int out_size) {
    (void)d_in; (void)in_sizes; (void)n_in;

    const int threads = 1024;
    int n4 = out_size >> 2;
    if ((out_size & 3) == 0 && (n4 % threads) == 0) {
        // Exact cover: no bounds check, no loop, no tail.
        zero_exact_f4<<<n4 / threads, threads>>>((float4*)d_out);
    } else {
        int blocks = (out_size + threads - 1) / threads;
        if (blocks > 1024) blocks = 1024;
        zero_general<<<blocks, threads>>>((float*)d_out, out_size);
    }
}

// round 5
// speedup vs baseline: 1.1625x; 1.1625x over previous
#include <cuda_runtime.h>

// TemporalAttention_43722767073503
//
// Reference output = log_softmax over a size-1 last axis of the (B,T,1) score
// tensor -> identically 0 for every finite input. The two GEMMs, tanh, and
// v-projection are all dead code; the exact answer is 524288 f32 zeros.
//
// Measured floor: ~3.9us kernel / ~5us wall regardless of grid shape (DRAM 0%,
// L2 5% -> stores are ~330 cyc; the rest is per-launch overhead + replay).
// This round: best-measured launch geometry (512 CTAs x 256 thr, R3's 5.06us
// wall) with the minimal branch-free body (one unconditional STG.128 per
// thread; 512*256*4 = 524288 floats exactly).

__global__ void zero_exact_512x256(float4* __restrict__ out) {
    out[blockIdx.x * blockDim.x + threadIdx.x] =
        make_float4(0.f, 0.f, 0.f, 0.f);
}

// General fallback (never taken for this problem's out_size; safety only).
__global__ void zero_general(float* __restrict__ out, int n) {
    for (int i = blockIdx.x * blockDim.x + threadIdx.x; i < n;
         i += gridDim.x * blockDim.x) {
        out[i] = 0.f;
    }
}

extern "C" void kernel_launch(void* const* d_in, const int* in_sizes, int n_in,
                              void* d_out, int out_size) {
    (void)d_in; (void)in_sizes; (void)n_in;

    const int threads = 256;
    int n4 = out_size >> 2;
    if ((out_size & 3) == 0 && (n4 % threads) == 0) {
        zero_exact_512x256<<<n4 / threads, threads>>>((float4*)d_out);
    } else {
        int blocks = (out_size + threads - 1) / threads;
        if (blocks > 1024) blocks = 1024;
        zero_general<<<blocks, threads>>>((float*)d_out, out_size);
    }
}